// round 15
// baseline (speedup 1.0000x reference)
#include <cuda_runtime.h>
#include <math.h>

// Problem constants
#define BB 8
#define DD 4096
#define NPROJ 12288      // 3*D
#define SS 16
#define FFD 16384
#define FIR_OFF 32768            // d_out offset of new_fir  (B*D elems of x first)
#define IIR_OFF 229376           // 32768 + 196608

typedef unsigned long long ull;

// ---------------- scratch (__device__ globals; no allocation allowed) -------
__device__ float g_xn1 [BB*DD];
__device__ float g_y   [BB*DD];
__device__ float g_xnew[BB*DD];
__device__ float g_ssq [BB];
// accumulators (atomically reduced GEMV outputs) — all L2-resident sized
__device__ float g_accP [BB*NPROJ];     // proj   (0.39 MB)
__device__ float g_accO [4*BB*DD];      // out_w  (0.5 MB, 4 stripes)
__device__ float g_accW1[BB*FFD];       // mlp_w1 (0.5 MB)
__device__ float g_accW3[BB*FFD];       // mlp_w3 (0.5 MB)
__device__ float g_accW2[4*BB*DD];      // mlp_w2 (0.5 MB, 4 stripes)

__device__ __forceinline__ void fma2(ull& a, ull w, ull x) {
    asm("fma.rn.f32x2 %0, %1, %2, %0;" : "+l"(a) : "l"(w), "l"(x));
}
__device__ __forceinline__ void cp_async16(void* sdst, const void* gsrc) {
    unsigned s = (unsigned)__cvta_generic_to_shared(sdst);
    asm volatile("cp.async.cg.shared.global [%0], [%1], 16;" :: "r"(s), "l"(gsrc));
}
__device__ __forceinline__ void cp_commit() {
    asm volatile("cp.async.commit_group;");
}
template<int N> __device__ __forceinline__ void cp_wait() {
    asm volatile("cp.async.wait_group %0;" :: "n"(N));
}
// PDL controls
__device__ __forceinline__ void pdl_wait() {
    asm volatile("griddepcontrol.wait;" ::: "memory");
}
__device__ __forceinline__ void pdl_trigger() {
    asm volatile("griddepcontrol.launch_dependents;");
}

// ---------------- rmsnorm of input x  (+ zero proj accumulator) -------------
__global__ void rmsnorm1_kernel(const float* __restrict__ x,
                                const float* __restrict__ w,
                                float* __restrict__ out,
                                float4* __restrict__ accP4) {
    int b = blockIdx.x;          // 8 blocks
    int tid = threadIdx.x;       // 512 threads
    // zero proj accumulator: 24576 float4 over 4096 threads = 6 each
    int gt = b*512 + tid;
    float4 z4 = make_float4(0.f,0.f,0.f,0.f);
#pragma unroll
    for (int i = 0; i < 6; i++) accP4[gt + i*4096] = z4;
    pdl_trigger();
    float v[8];
    float ss = 0.f;
#pragma unroll
    for (int e = 0; e < 8; e++) {
        float t = x[b*DD + e*512 + tid];
        v[e] = t; ss += t*t;
    }
    __shared__ float red[16];
    int lane = tid & 31, wid = tid >> 5;
#pragma unroll
    for (int o = 16; o; o >>= 1) ss += __shfl_xor_sync(0xffffffffu, ss, o);
    if (lane == 0) red[wid] = ss;
    __syncthreads();
    if (tid == 0) { float t = 0.f; for (int i = 0; i < 16; i++) t += red[i]; red[0] = t; }
    __syncthreads();
    float scale = rsqrtf(red[0] * (1.f/DD) + 1e-6f);
#pragma unroll
    for (int e = 0; e < 8; e++)
        out[b*DD + e*512 + tid] = v[e] * scale * w[e*512 + tid];
}

// ---------------- split-K GEMV -> atomic float4 accumulation ----------------
// stripe4: float4 stride between accumulator stripes (0 = single buffer);
// block RED-s into stripe (blockIdx.y & 3).
template<int KCH>
__global__ __launch_bounds__(256, 2)
void gemv_partial(const float* __restrict__ W,
                  const float* __restrict__ X,
                  float* __restrict__ P, int K, int N, int stripe4) {
    extern __shared__ char smem[];
    float2*     xs2  = reinterpret_cast<float2*>(smem);                 // 8*KCH
    ulonglong2* wbuf = reinterpret_cast<ulonglong2*>(smem + 8*KCH*8);   // 2*8*256

    int tid = threadIdx.x;               // 256 threads
    int k0  = blockIdx.y * KCH;
    int Nv = N >> 2;                     // float4 columns
    int col4 = blockIdx.x*256 + tid;
    const float4* Wv = reinterpret_cast<const float4*>(W) + (size_t)k0*Nv + col4;

    // weight prefetch (independent of predecessor output)
#pragma unroll
    for (int i = 0; i < 8; i++)
        cp_async16(&wbuf[(0*8 + i)*256 + tid], Wv + (size_t)i*Nv);
    cp_commit();
#pragma unroll
    for (int i = 0; i < 8; i++)
        cp_async16(&wbuf[(1*8 + i)*256 + tid], Wv + (size_t)(8+i)*Nv);
    cp_commit();

    pdl_trigger();
    pdl_wait();                          // predecessor output (X, zeroed P) visible

#pragma unroll
    for (int i = tid; i < 8*KCH; i += 256) {
        int b = i / KCH, k = i % KCH;
        float v = X[b*K + k0 + k];
        xs2[i] = make_float2(v, v);
    }
    __syncthreads();

    ull acc[8][2];
#pragma unroll
    for (int b = 0; b < 8; b++) { acc[b][0] = 0ull; acc[b][1] = 0ull; }

    const int nstages = KCH / 8;
#pragma unroll 1
    for (int s = 0; s < nstages; s++) {
        if (s + 1 < nstages) cp_wait<1>(); else cp_wait<0>();
        int sb = s & 1;
        const ulonglong2* ws = wbuf + sb*2048 + tid;
        int kb = s*8;
#pragma unroll
        for (int i = 0; i < 8; i++) {
            ulonglong2 wv = ws[i*256];
#pragma unroll
            for (int b = 0; b < 8; b++) {
                ull xx = *reinterpret_cast<const ull*>(&xs2[b*KCH + kb + i]);
                fma2(acc[b][0], wv.x, xx);
                fma2(acc[b][1], wv.y, xx);
            }
        }
        if (s + 2 < nstages) {
            const float4* src = Wv + (size_t)(s+2)*8*Nv;
#pragma unroll
            for (int i = 0; i < 8; i++)
                cp_async16(&wbuf[(sb*8 + i)*256 + tid], src + (size_t)i*Nv);
            cp_commit();
        }
    }

    float4* Pv = reinterpret_cast<float4*>(P) + (size_t)(blockIdx.y & 3)*stripe4 + col4;
#pragma unroll
    for (int b = 0; b < 8; b++) {
        float4 v;
        *reinterpret_cast<ull*>(&v.x) = acc[b][0];
        *reinterpret_cast<ull*>(&v.z) = acc[b][1];
        atomicAdd(&Pv[(size_t)b*Nv], v);
    }
}

// ---------------- w2 GEMV with fused SwiGLU activation ----------------------
// activation = silu(accW1[b][k]) * accW3[b][k], computed inline (no g buffer)
template<int KCH>
__global__ __launch_bounds__(256, 2)
void gemv_w2(const float* __restrict__ W,
             const float* __restrict__ A,      // accW1
             const float* __restrict__ C,      // accW3
             float* __restrict__ P, int K, int N, int stripe4) {
    extern __shared__ char smem[];
    float2*     xs2  = reinterpret_cast<float2*>(smem);                 // 8*KCH
    ulonglong2* wbuf = reinterpret_cast<ulonglong2*>(smem + 8*KCH*8);   // 2*8*256

    int tid = threadIdx.x;
    int k0  = blockIdx.y * KCH;
    int Nv = N >> 2;
    int col4 = blockIdx.x*256 + tid;
    const float4* Wv = reinterpret_cast<const float4*>(W) + (size_t)k0*Nv + col4;

#pragma unroll
    for (int i = 0; i < 8; i++)
        cp_async16(&wbuf[(0*8 + i)*256 + tid], Wv + (size_t)i*Nv);
    cp_commit();
#pragma unroll
    for (int i = 0; i < 8; i++)
        cp_async16(&wbuf[(1*8 + i)*256 + tid], Wv + (size_t)(8+i)*Nv);
    cp_commit();

    pdl_trigger();
    pdl_wait();                          // accW1/accW3 complete; accW2 zeroed

#pragma unroll
    for (int i = tid; i < 8*KCH; i += 256) {
        int b = i / KCH, k = i % KCH;
        int idx = b*K + k0 + k;
        float a = A[idx], c = C[idx];
        float v = (a / (1.f + __expf(-a))) * c;
        xs2[i] = make_float2(v, v);
    }
    __syncthreads();

    ull acc[8][2];
#pragma unroll
    for (int b = 0; b < 8; b++) { acc[b][0] = 0ull; acc[b][1] = 0ull; }

    const int nstages = KCH / 8;
#pragma unroll 1
    for (int s = 0; s < nstages; s++) {
        if (s + 1 < nstages) cp_wait<1>(); else cp_wait<0>();
        int sb = s & 1;
        const ulonglong2* ws = wbuf + sb*2048 + tid;
        int kb = s*8;
#pragma unroll
        for (int i = 0; i < 8; i++) {
            ulonglong2 wv = ws[i*256];
#pragma unroll
            for (int b = 0; b < 8; b++) {
                ull xx = *reinterpret_cast<const ull*>(&xs2[b*KCH + kb + i]);
                fma2(acc[b][0], wv.x, xx);
                fma2(acc[b][1], wv.y, xx);
            }
        }
        if (s + 2 < nstages) {
            const float4* src = Wv + (size_t)(s+2)*8*Nv;
#pragma unroll
            for (int i = 0; i < 8; i++)
                cp_async16(&wbuf[(sb*8 + i)*256 + tid], src + (size_t)i*Nv);
            cp_commit();
        }
    }

    float4* Pv = reinterpret_cast<float4*>(P) + (size_t)(blockIdx.y & 3)*stripe4 + col4;
#pragma unroll
    for (int b = 0; b < 8; b++) {
        float4 v;
        *reinterpret_cast<ull*>(&v.x) = acc[b][0];
        *reinterpret_cast<ull*>(&v.z) = acc[b][1];
        atomicAdd(&Pv[(size_t)b*Nv], v);
    }
}

// ---------------- dual GEMV for w1/w3 with fused post-norm scaling ----------
template<int KCH>
__global__ __launch_bounds__(256, 2)
void gemv_dual(const float* __restrict__ W1,
               const float* __restrict__ W3,
               const float* __restrict__ Xnew,
               const float* __restrict__ PostW,
               float* __restrict__ P1,
               float* __restrict__ P3, int K, int N) {
    extern __shared__ char smem[];
    float2*     xs2  = reinterpret_cast<float2*>(smem);
    ulonglong2* wbuf = reinterpret_cast<ulonglong2*>(smem + 8*KCH*8);

    const float* W = blockIdx.z ? W3 : W1;
    float*       P = blockIdx.z ? P3 : P1;

    int tid = threadIdx.x;
    int k0  = blockIdx.y * KCH;
    int Nv = N >> 2;
    int col4 = blockIdx.x*256 + tid;
    const float4* Wv = reinterpret_cast<const float4*>(W) + (size_t)k0*Nv + col4;

#pragma unroll
    for (int i = 0; i < 8; i++)
        cp_async16(&wbuf[(0*8 + i)*256 + tid], Wv + (size_t)i*Nv);
    cp_commit();
#pragma unroll
    for (int i = 0; i < 8; i++)
        cp_async16(&wbuf[(1*8 + i)*256 + tid], Wv + (size_t)(8+i)*Nv);
    cp_commit();

    pdl_trigger();
    pdl_wait();                          // xnew + g_ssq + zeroed accums valid

    float rs[BB];
#pragma unroll
    for (int b = 0; b < BB; b++)
        rs[b] = rsqrtf(g_ssq[b] * (1.f/DD) + 1e-6f);
#pragma unroll
    for (int i = tid; i < 8*KCH; i += 256) {
        int b = i / KCH, k = i % KCH;
        float v = Xnew[b*K + k0 + k] * rs[b] * PostW[k0 + k];
        xs2[i] = make_float2(v, v);
    }
    __syncthreads();

    ull acc[8][2];
#pragma unroll
    for (int b = 0; b < 8; b++) { acc[b][0] = 0ull; acc[b][1] = 0ull; }

    const int nstages = KCH / 8;
#pragma unroll 1
    for (int s = 0; s < nstages; s++) {
        if (s + 1 < nstages) cp_wait<1>(); else cp_wait<0>();
        int sb = s & 1;
        const ulonglong2* ws = wbuf + sb*2048 + tid;
        int kb = s*8;
#pragma unroll
        for (int i = 0; i < 8; i++) {
            ulonglong2 wv = ws[i*256];
#pragma unroll
            for (int b = 0; b < 8; b++) {
                ull xx = *reinterpret_cast<const ull*>(&xs2[b*KCH + kb + i]);
                fma2(acc[b][0], wv.x, xx);
                fma2(acc[b][1], wv.y, xx);
            }
        }
        if (s + 2 < nstages) {
            const float4* src = Wv + (size_t)(s+2)*8*Nv;
#pragma unroll
            for (int i = 0; i < 8; i++)
                cp_async16(&wbuf[(sb*8 + i)*256 + tid], src + (size_t)i*Nv);
            cp_commit();
        }
    }

    float4* Pv = reinterpret_cast<float4*>(P) + col4;
#pragma unroll
    for (int b = 0; b < 8; b++) {
        float4 v;
        *reinterpret_cast<ull*>(&v.x) = acc[b][0];
        *reinterpret_cast<ull*>(&v.z) = acc[b][1];
        atomicAdd(&Pv[(size_t)b*Nv], v);
    }
}

// ---------------- FIR + gating split + IIR (single-read z, zero accO) -------
__global__ void fir_iir_kernel(const float* __restrict__ P,
                               const float* __restrict__ fir_state,
                               const float* __restrict__ sfw,
                               const float* __restrict__ sfb,
                               const float* __restrict__ iir,
                               const float* __restrict__ lp,
                               const float* __restrict__ resid,
                               const float* __restrict__ Dres,
                               float* __restrict__ y,
                               float* __restrict__ dout,
                               float4* __restrict__ accO4) {
    __shared__ float zps[384];
    pdl_trigger();
    pdl_wait();                          // proj accumulation complete
    int blk = blockIdx.x;                // 256 blocks = 8 batch * 32 heads
    int b = blk >> 5, h = blk & 31;
    int tid = threadIdx.x;               // 384 threads
    int e = tid >> 7, j = tid & 127;
    if (blk == 0 && tid < BB) g_ssq[tid] = 0.f;
    // zero out_w accumulator (4 stripes): 32768 float4 over 256 blocks x 128 thr
    if (tid < 128) accO4[blk*128 + tid] = make_float4(0.f,0.f,0.f,0.f);

    {
        int i  = h*384 + e*128 + j;
        int gi = b*NPROJ + i;
        float u = P[gi];
        float f0 = fir_state[gi*2 + 0];
        float f1 = fir_state[gi*2 + 1];
        float w0 = sfw[i*3 + 0], w1 = sfw[i*3 + 1], w2 = sfw[i*3 + 2];
        zps[tid] = w2*u + f0*w0 + f1*w1 + sfb[i];
        dout[FIR_OFF + gi*2 + 0] = f1;   // new_fir = [f1, u]
        dout[FIR_OFF + gi*2 + 1] = u;
    }
    __syncthreads();
    if (tid < 128) {
        int d = h*128 + tid;
        float x2 = zps[tid], x1 = zps[128+tid], v = zps[256+tid];
        float x1v = x1 * v;
        float res = 0.f;
        int base = (b*DD + d)*SS;
#pragma unroll
        for (int s = 0; s < SS; s++) {
            float pole = __expf(lp[d*SS + s]);
            float ni = fmaf(pole, iir[base + s], x1v);
            dout[IIR_OFF + base + s] = ni;
            res = fmaf(resid[d*SS + s], ni, res);
        }
        y[b*DD + d] = x2 * (res + Dres[d]*x1v);
    }
}

// ---- xnew = sum4(accO) + bias + residual + ssq; zero accW1/W3/W2 -----------
__global__ void reduce_res_kernel(const float4* __restrict__ accO4,
                                  const float4* __restrict__ x4,
                                  const float4* __restrict__ ob4,
                                  float4* __restrict__ xnew4,
                                  float4* __restrict__ accW1_4,
                                  float4* __restrict__ accW3_4,
                                  float4* __restrict__ accW2_4) {
    pdl_trigger();
    pdl_wait();
    int gid = blockIdx.x*256 + threadIdx.x;   // 256 blocks x 256 = 65536
    float4 z4 = make_float4(0.f,0.f,0.f,0.f);
    accW1_4[gid] = z4;                        // zero 2 x 32768 float4
    accW3_4[gid] = z4;
    if (gid < 32768) accW2_4[gid] = z4;       // zero all 4 w2 stripes
    if (gid < 8192) {
        int b = gid >> 10;
        float4 o = ob4[gid & 1023];
        float4 r = x4[gid];
        r.x += o.x; r.y += o.y; r.z += o.z; r.w += o.w;
#pragma unroll
        for (int s = 0; s < 4; s++) {
            float4 p = accO4[s*8192 + gid];
            r.x += p.x; r.y += p.y; r.z += p.z; r.w += p.w;
        }
        xnew4[gid] = r;
        float ss = r.x*r.x + r.y*r.y + r.z*r.z + r.w*r.w;
#pragma unroll
        for (int o2 = 16; o2; o2 >>= 1) ss += __shfl_xor_sync(0xffffffffu, ss, o2);
        if ((threadIdx.x & 31) == 0) atomicAdd(&g_ssq[b], ss);
    }
}

// ---------------- final: x_out = xnew + sum4(accW2) --------------------------
__global__ void final_kernel(const float4* __restrict__ accW2_4,
                             const float4* __restrict__ xnew4,
                             float4* __restrict__ dout4) {
    pdl_trigger();
    pdl_wait();
    int gid = blockIdx.x*256 + threadIdx.x;   // 32 blocks x 256 = 8192
    float4 r = xnew4[gid];
#pragma unroll
    for (int s = 0; s < 4; s++) {
        float4 p = accW2_4[s*8192 + gid];
        r.x += p.x; r.y += p.y; r.z += p.z; r.w += p.w;
    }
    dout4[gid] = r;
}

// ---------------- host launcher ----------------------------------------------
static void launch_pdl(const void* func, dim3 grid, dim3 block, size_t smem,
                       void** args) {
    cudaLaunchConfig_t cfg = {};
    cfg.gridDim = grid;
    cfg.blockDim = block;
    cfg.dynamicSmemBytes = smem;
    cfg.stream = 0;
    cudaLaunchAttribute attr[1];
    attr[0].id = cudaLaunchAttributeProgrammaticStreamSerialization;
    attr[0].val.programmaticStreamSerializationAllowed = 1;
    cfg.attrs = attr;
    cfg.numAttrs = 1;
    cudaLaunchKernelExC(&cfg, func, args);
}

extern "C" void kernel_launch(void* const* d_in, const int* in_sizes, int n_in,
                              void* d_out, int out_size) {
    (void)in_sizes; (void)n_in; (void)out_size;
    const float* x          = (const float*)d_in[0];
    const float* fir_state  = (const float*)d_in[1];
    const float* iir_state  = (const float*)d_in[2];
    const float* pre_w      = (const float*)d_in[3];
    const float* proj_w     = (const float*)d_in[4];
    const float* sfw        = (const float*)d_in[5];
    const float* sfb        = (const float*)d_in[6];
    const float* Dres       = (const float*)d_in[7];
    const float* resid      = (const float*)d_in[8];
    const float* lp         = (const float*)d_in[9];
    const float* out_w      = (const float*)d_in[10];
    const float* out_b      = (const float*)d_in[11];
    const float* post_w     = (const float*)d_in[12];
    const float* w1         = (const float*)d_in[13];
    const float* w3         = (const float*)d_in[14];
    const float* w2         = (const float*)d_in[15];
    float* out = (float*)d_out;

    float *xn1, *y, *xnew, *aP, *aO, *aW1, *aW3, *aW2;
    cudaGetSymbolAddress((void**)&xn1,  g_xn1);
    cudaGetSymbolAddress((void**)&y,    g_y);
    cudaGetSymbolAddress((void**)&xnew, g_xnew);
    cudaGetSymbolAddress((void**)&aP,   g_accP);
    cudaGetSymbolAddress((void**)&aO,   g_accO);
    cudaGetSymbolAddress((void**)&aW1,  g_accW1);
    cudaGetSymbolAddress((void**)&aW3,  g_accW3);
    cudaGetSymbolAddress((void**)&aW2,  g_accW2);

    const int smem256 = 8*256*8 + 65536;   // 81920
    const int smem64  = 8*64*8  + 65536;   // 69632
    const int smem512 = 8*512*8 + 65536;   // 98304
    cudaFuncSetAttribute((const void*)gemv_partial<256>,
                         cudaFuncAttributeMaxDynamicSharedMemorySize, smem256);
    cudaFuncSetAttribute((const void*)gemv_partial<64>,
                         cudaFuncAttributeMaxDynamicSharedMemorySize, smem64);
    cudaFuncSetAttribute((const void*)gemv_w2<256>,
                         cudaFuncAttributeMaxDynamicSharedMemorySize, smem256);
    cudaFuncSetAttribute((const void*)gemv_dual<512>,
                         cudaFuncAttributeMaxDynamicSharedMemorySize, smem512);

    int K1 = DD, N1 = NPROJ, N2 = DD, N3 = FFD, K3 = FFD;
    int strideZero = 0, strideBD = BB*DD/4;   // float4 units (8192)

    // 1. pre-norm + zero proj accumulator (normal launch; per-replay barrier)
    {
        float4* aP4 = (float4*)aP;
        rmsnorm1_kernel<<<BB, 512>>>(x, pre_w, xn1, aP4);
    }
    // 2. z = xn1 @ proj_w -> accP: 12 col x 16 chunks = 192 blocks
    {
        void* a[] = {&proj_w, &xn1, &aP, &K1, &N1, &strideZero};
        launch_pdl((const void*)gemv_partial<256>, dim3(12,16), dim3(256), smem256, a);
    }
    // 3. FIR + split + IIR -> y, new_fir, new_iir; zero g_ssq + accO stripes
    {
        float4* aO4 = (float4*)aO;
        void* a[] = {&aP, &fir_state, &sfw, &sfb, &iir_state, &lp, &resid, &Dres, &y, &out, &aO4};
        launch_pdl((const void*)fir_iir_kernel, dim3(256), dim3(384), 0, a);
    }
    // 4. y @ out_w -> accO (4-way striped): 4 col x 64 chunks = 256 blocks
    {
        void* a[] = {&out_w, &y, &aO, &K1, &N2, &strideBD};
        launch_pdl((const void*)gemv_partial<64>, dim3(4,64), dim3(256), smem64, a);
    }
    // 5. xnew = sum4(accO) + out_b + x; ssq; zero accW1/accW3/accW2
    {
        const float4 *aO4 = (const float4*)aO, *x4 = (const float4*)x,
                     *o4 = (const float4*)out_b;
        float4 *xn4 = (float4*)xnew, *w14 = (float4*)aW1, *w34 = (float4*)aW3,
               *w24 = (float4*)aW2;
        void* a[] = {&aO4, &x4, &o4, &xn4, &w14, &w34, &w24};
        launch_pdl((const void*)reduce_res_kernel, dim3(256), dim3(256), 0, a);
    }
    // 6. fused MLP up with post-norm -> accW1/accW3: 16 col x 8 x 2 = 256 blocks
    {
        void* a[] = {&w1, &w3, &xnew, &post_w, &aW1, &aW3, &K1, &N3};
        launch_pdl((const void*)gemv_dual<512>, dim3(16,8,2), dim3(256), smem512, a);
    }
    // 7. w2 GEMV with fused SwiGLU -> accW2 (4-way striped): 4 col x 64 chunks
    {
        void* a[] = {&w2, &aW1, &aW3, &aW2, &K3, &N2, &strideBD};
        launch_pdl((const void*)gemv_w2<256>, dim3(4,64), dim3(256), smem256, a);
    }
    // 8. x_out = xnew + sum4(accW2)
    {
        const float4 *w24 = (const float4*)aW2, *xn4c = (const float4*)xnew;
        float4* d4 = (float4*)out;
        void* a[] = {&w24, &xn4c, &d4};
        launch_pdl((const void*)final_kernel, dim3(32), dim3(256), 0, a);
    }
}